// round 14
// baseline (speedup 1.0000x reference)
#include <cuda_runtime.h>
#include <cstdint>
#include <math.h>

// ---------------------------------------------------------------------------
// Problem constants
// ---------------------------------------------------------------------------
constexpr int Mtok  = 2048;
constexpr int Kdim  = 2048;
constexpr int Ndim  = 1408;
constexpr int NE    = 8;
constexpr int CAP   = 1024;
constexpr int RROWS = 4096;

// Scratch
__device__ int   g_count[NE];
__device__ int   g_rowtok[NE * CAP];
__device__ float g_rowgate[NE * CAP];
__device__ float g_xr[(size_t)Mtok * Kdim];      // tf32-rounded X
__device__ float g_h[(size_t)NE * CAP * Ndim];   // tf32-rounded activations

// ---------------------------------------------------------------------------
// Helpers
// ---------------------------------------------------------------------------
__device__ __forceinline__ uint32_t smem_u32(const void* p) {
    uint32_t a;
    asm("{ .reg .u64 t; cvta.to.shared.u64 t, %1; cvt.u32.u64 %0, t; }"
        : "=r"(a) : "l"(p));
    return a;
}
__device__ __forceinline__ uint32_t f2tf(float x) {
    uint32_t r; asm("cvt.rna.tf32.f32 %0, %1;" : "=r"(r) : "f"(x)); return r;
}
__device__ __forceinline__ uint4 tf4(float4 v) {
    return make_uint4(f2tf(v.x), f2tf(v.y), f2tf(v.z), f2tf(v.w));
}
__device__ __forceinline__ void mma8(float c[4], const uint32_t a[4],
                                     uint32_t b0, uint32_t b1) {
    asm volatile(
        "mma.sync.aligned.m16n8k8.row.col.f32.tf32.tf32.f32 "
        "{%0,%1,%2,%3}, {%4,%5,%6,%7}, {%8,%9}, {%0,%1,%2,%3};"
        : "+f"(c[0]), "+f"(c[1]), "+f"(c[2]), "+f"(c[3])
        : "r"(a[0]), "r"(a[1]), "r"(a[2]), "r"(a[3]), "r"(b0), "r"(b1));
}
__device__ __forceinline__ void ldsm4(uint32_t* r, uint32_t addr) {
    asm volatile("ldmatrix.sync.aligned.m8n8.x4.shared.b16 {%0,%1,%2,%3}, [%4];"
                 : "=r"(r[0]), "=r"(r[1]), "=r"(r[2]), "=r"(r[3]) : "r"(addr));
}
__device__ __forceinline__ void cp16(uint32_t dst, const void* src) {
    asm volatile("cp.async.cg.shared.global [%0], [%1], 16;"
                 :: "r"(dst), "l"(src));
}
__device__ __forceinline__ void cp_commit() {
    asm volatile("cp.async.commit_group;" ::: "memory");
}
__device__ __forceinline__ void cp_wait0() {
    asm volatile("cp.async.wait_group 0;" ::: "memory");
}
// 256B-row swizzle: 16 chunks of 16B; keep bit3, XOR low3 with row&7
__device__ __forceinline__ int sw256(int chunk, int row) {
    return ((chunk & 8) | ((chunk & 7) ^ (row & 7))) << 4;
}

// ---------------------------------------------------------------------------
// Prep kernels
// ---------------------------------------------------------------------------
__global__ void k_prep(float* __restrict__ out, const float* __restrict__ X) {
    int idx = blockIdx.x * blockDim.x + threadIdx.x;
    if (idx < Mtok * Kdim / 4) {
        reinterpret_cast<float4*>(out)[idx] = make_float4(0.f, 0.f, 0.f, 0.f);
        reinterpret_cast<uint4*>(g_xr)[idx] =
            tf4(reinterpret_cast<const float4*>(X)[idx]);
    }
    if (idx < NE) g_count[idx] = 0;
}
__global__ void k_route(const int* __restrict__ flat_idx,
                        const float* __restrict__ flat_gate) {
    int r = blockIdx.x * blockDim.x + threadIdx.x;
    if (r >= RROWS) return;
    int e = flat_idx[r];
    if (e < 0 || e >= NE) return;
    int pos = atomicAdd(&g_count[e], 1);
    if (pos < CAP) {
        g_rowtok[e * CAP + pos]  = r >> 1;
        g_rowgate[e * CAP + pos] = flat_gate[r];
    }
}

// ---------------------------------------------------------------------------
// gemm1: gate+up. Block 128 rows x 128 n, BK=64. 512 threads, 16 warps (2x8);
// warp tile 64 rows x 16 n per matrix (G and U). Hidden stage barrier.
// ---------------------------------------------------------------------------
constexpr int G1_A = 0, G1_BG = 32768, G1_BU = 65536, G1_STAGE = 98304;
constexpr int G1_SMEM = 2 * G1_STAGE;   // 192 KB

__global__ __launch_bounds__(512)
void k_gemm1(const float* __restrict__ GW, const float* __restrict__ UW) {
    extern __shared__ char smem[];
    const int e    = blockIdx.z;
    const int cnt  = min(g_count[e], CAP);
    const int row0 = blockIdx.y * 128;
    if (row0 >= cnt) return;
    const int n0  = blockIdx.x * 128;
    const int tid = threadIdx.x;
    const uint32_t sb = smem_u32(smem);

    // ---- staging ids: 8 thr/row, rows {srow, srow+64}, chunks {schk, schk+8}
    const int srow = tid >> 3, schk = tid & 7;
    int oA[2][2];
    const float* asrc[2];
    const float* gsrc[2];
    const float* usrc[2];
#pragma unroll
    for (int p = 0; p < 2; p++) {
        const int r = srow + 64 * p;
#pragma unroll
        for (int j = 0; j < 2; j++)
            oA[p][j] = r * 256 + sw256(schk + 8 * j, r);
        int tok = g_rowtok[e * CAP + row0 + r];
        asrc[p] = g_xr + (size_t)tok * Kdim + schk * 4;
        gsrc[p] = GW + ((size_t)e * Ndim + n0 + r) * Kdim + schk * 4;
        usrc[p] = UW + ((size_t)e * Ndim + n0 + r) * Kdim + schk * 4;
    }

    // ---- compute ids ----
    const int wid = tid >> 5, L = tid & 31;
    const int wm = (wid >> 3) * 64, wn = (wid & 7) * 16;
    const int lr = L >> 2, lc = L & 3;
    const int rowoffA = ((L >> 3) & 1) * 8 + (L & 7);
    const int hiA = L >> 4;
    const int rowoffB = ((L >> 4) & 1) * 8 + (L & 7);
    const int hiB = (L >> 3) & 1;
    const int lx = L & 7;
    uint32_t rA[4];
#pragma unroll
    for (int mf = 0; mf < 4; mf++)
        rA[mf] = sb + G1_A + (wm + mf * 16 + rowoffA) * 256;
    const uint32_t rBg = sb + G1_BG + (wn + rowoffB) * 256;
    const uint32_t rBu = sb + G1_BU + (wn + rowoffB) * 256;

    float accG[4][2][4], accU[4][2][4];
#pragma unroll
    for (int mf = 0; mf < 4; mf++)
#pragma unroll
        for (int nf = 0; nf < 2; nf++)
#pragma unroll
            for (int q = 0; q < 4; q++) { accG[mf][nf][q] = 0.f; accU[mf][nf][q] = 0.f; }

    // ---- prologue: stage 0 ----
#pragma unroll
    for (int p = 0; p < 2; p++)
#pragma unroll
        for (int j = 0; j < 2; j++)
            cp16(sb + G1_A + oA[p][j], asrc[p] + 32 * j);
    cp_commit();
    {
        float4 w[2][2];
#pragma unroll
        for (int p = 0; p < 2; p++)
#pragma unroll
            for (int j = 0; j < 2; j++)
                w[p][j] = *reinterpret_cast<const float4*>(gsrc[p] + 32 * j);
#pragma unroll
        for (int p = 0; p < 2; p++)
#pragma unroll
            for (int j = 0; j < 2; j++)
                *reinterpret_cast<uint4*>(smem + G1_BG + oA[p][j]) = tf4(w[p][j]);
#pragma unroll
        for (int p = 0; p < 2; p++)
#pragma unroll
            for (int j = 0; j < 2; j++)
                w[p][j] = *reinterpret_cast<const float4*>(usrc[p] + 32 * j);
#pragma unroll
        for (int p = 0; p < 2; p++)
#pragma unroll
            for (int j = 0; j < 2; j++)
                *reinterpret_cast<uint4*>(smem + G1_BU + oA[p][j]) = tf4(w[p][j]);
    }
    cp_wait0();
    __syncthreads();

    const int KT = Kdim / 64;   // 32 stages
    float4 wst[2][2];
    for (int kt = 0; kt < KT; ++kt) {
        const int cur = (kt & 1) * G1_STAGE;
        const int nxt = ((kt + 1) & 1) * G1_STAGE;
        const bool more = (kt + 1 < KT);
        const int ko = (kt + 1) * 64;
        if (more) {
#pragma unroll
            for (int p = 0; p < 2; p++)
#pragma unroll
                for (int j = 0; j < 2; j++)
                    cp16(sb + nxt + G1_A + oA[p][j], asrc[p] + ko + 32 * j);
            cp_commit();
        }
#pragma unroll
        for (int c = 0; c < 8; c++) {
            uint32_t a[4][4], bg[4], bu[4];
            const uint32_t swA = (uint32_t)((((2 * c + hiA) & 8) |
                                            (((2 * c + hiA) & 7) ^ lx)) << 4) + cur;
            const uint32_t swB = (uint32_t)((((2 * c + hiB) & 8) |
                                            (((2 * c + hiB) & 7) ^ lx)) << 4) + cur;
#pragma unroll
            for (int mf = 0; mf < 4; mf++) ldsm4(a[mf], rA[mf] + swA);
            ldsm4(bg, rBg + swB);
            ldsm4(bu, rBu + swB);
            // hidden stage barrier: all reads of `cur` done; mma(7) from regs
            if (c == 7) { cp_wait0(); __syncthreads(); }
#pragma unroll
            for (int mf = 0; mf < 4; mf++) {
                mma8(accG[mf][0], a[mf], bg[0], bg[1]);
                mma8(accG[mf][1], a[mf], bg[2], bg[3]);
                mma8(accU[mf][0], a[mf], bu[0], bu[1]);
                mma8(accU[mf][1], a[mf], bu[2], bu[3]);
            }
            if (more) {
                if (c == 0) {
#pragma unroll
                    for (int p = 0; p < 2; p++)
#pragma unroll
                        for (int j = 0; j < 2; j++)
                            wst[p][j] = *reinterpret_cast<const float4*>(gsrc[p] + ko + 32 * j);
                } else if (c == 2) {
#pragma unroll
                    for (int p = 0; p < 2; p++)
#pragma unroll
                        for (int j = 0; j < 2; j++)
                            *reinterpret_cast<uint4*>(smem + nxt + G1_BG + oA[p][j]) = tf4(wst[p][j]);
#pragma unroll
                    for (int p = 0; p < 2; p++)
#pragma unroll
                        for (int j = 0; j < 2; j++)
                            wst[p][j] = *reinterpret_cast<const float4*>(usrc[p] + ko + 32 * j);
                } else if (c == 4) {
#pragma unroll
                    for (int p = 0; p < 2; p++)
#pragma unroll
                        for (int j = 0; j < 2; j++)
                            *reinterpret_cast<uint4*>(smem + nxt + G1_BU + oA[p][j]) = tf4(wst[p][j]);
                }
            }
        }
    }

    // ---- SwiGLU epilogue -> g_h (tf32-rounded) ----
#pragma unroll
    for (int mf = 0; mf < 4; mf++) {
#pragma unroll
        for (int half = 0; half < 2; half++) {
            const int grow = row0 + wm + mf * 16 + half * 8 + lr;
            if (grow >= cnt) continue;
            float* hrow = g_h + ((size_t)e * CAP + grow) * Ndim;
#pragma unroll
            for (int nf = 0; nf < 2; nf++) {
                const int col = n0 + wn + nf * 8 + 2 * lc;
                float2 o;
#pragma unroll
                for (int q = 0; q < 2; q++) {
                    float g = fminf(accG[mf][nf][half * 2 + q], 10.f);
                    float u = fminf(fmaxf(accU[mf][nf][half * 2 + q], -10.f), 10.f);
                    float h = (g / (1.f + expf(-g))) * u;
                    (&o.x)[q] = __uint_as_float(f2tf(h));
                }
                *reinterpret_cast<float2*>(hrow + col) = o;
            }
        }
    }
}

// ---------------------------------------------------------------------------
// gemm2: down. Block 128 rows x 256 k-out, BK=64 over N. 512 threads, 16
// warps (2x8); warp tile 64x32. Hidden stage barrier.
// ---------------------------------------------------------------------------
constexpr int G2_A = 0, G2_B = 32768, G2_STAGE = 98304;
constexpr int G2_SMEM = 2 * G2_STAGE;   // 192 KB

__global__ __launch_bounds__(512)
void k_gemm2(const float* __restrict__ DW, float* __restrict__ out) {
    extern __shared__ char smem[];
    const int e    = blockIdx.z;
    const int cnt  = min(g_count[e], CAP);
    const int row0 = blockIdx.y * 128;
    if (row0 >= cnt) return;
    const int k0  = blockIdx.x * 256;
    const int tid = threadIdx.x;
    const uint32_t sb = smem_u32(smem);

    const int srow = tid >> 3, schk = tid & 7;
    int oA[2][2], oB[4][2];
    const float* ha[2];
    const float* bsrc[4];
#pragma unroll
    for (int p = 0; p < 2; p++) {
        const int r = srow + 64 * p;
#pragma unroll
        for (int j = 0; j < 2; j++) oA[p][j] = r * 256 + sw256(schk + 8 * j, r);
        ha[p] = g_h + ((size_t)e * CAP + row0 + r) * Ndim + schk * 4;
    }
#pragma unroll
    for (int p = 0; p < 4; p++) {
        const int r = srow + 64 * p;
#pragma unroll
        for (int j = 0; j < 2; j++) oB[p][j] = r * 256 + sw256(schk + 8 * j, r);
        bsrc[p] = DW + ((size_t)e * Kdim + k0 + r) * Ndim + schk * 4;
    }

    const int wid = tid >> 5, L = tid & 31;
    const int wm = (wid >> 3) * 64, wn = (wid & 7) * 32;
    const int lr = L >> 2, lc = L & 3;
    const int rowoffA = ((L >> 3) & 1) * 8 + (L & 7);
    const int hiA = L >> 4;
    const int rowoffB = ((L >> 4) & 1) * 8 + (L & 7);
    const int hiB = (L >> 3) & 1;
    const int lx = L & 7;
    uint32_t rA[4], rB[2];
#pragma unroll
    for (int mf = 0; mf < 4; mf++)
        rA[mf] = sb + G2_A + (wm + mf * 16 + rowoffA) * 256;
#pragma unroll
    for (int h = 0; h < 2; h++)
        rB[h] = sb + G2_B + (wn + h * 16 + rowoffB) * 256;

    float acc[4][4][4];
#pragma unroll
    for (int mf = 0; mf < 4; mf++)
#pragma unroll
        for (int nf = 0; nf < 4; nf++)
#pragma unroll
            for (int q = 0; q < 4; q++) acc[mf][nf][q] = 0.f;

    // prologue stage 0
#pragma unroll
    for (int p = 0; p < 2; p++)
#pragma unroll
        for (int j = 0; j < 2; j++)
            cp16(sb + G2_A + oA[p][j], ha[p] + 32 * j);
    cp_commit();
    {
        float4 w;
#pragma unroll
        for (int p = 0; p < 4; p++)
#pragma unroll
            for (int j = 0; j < 2; j++) {
                w = *reinterpret_cast<const float4*>(bsrc[p] + 32 * j);
                *reinterpret_cast<uint4*>(smem + G2_B + oB[p][j]) = tf4(w);
            }
    }
    cp_wait0();
    __syncthreads();

    const int KT = Ndim / 64;   // 22 stages
    float4 wst[2][2];
    for (int kt = 0; kt < KT; ++kt) {
        const int cur = (kt & 1) * G2_STAGE;
        const int nxt = ((kt + 1) & 1) * G2_STAGE;
        const bool more = (kt + 1 < KT);
        const int ko = (kt + 1) * 64;
        if (more) {
#pragma unroll
            for (int p = 0; p < 2; p++)
#pragma unroll
                for (int j = 0; j < 2; j++)
                    cp16(sb + nxt + G2_A + oA[p][j], ha[p] + ko + 32 * j);
            cp_commit();
        }
#pragma unroll
        for (int c = 0; c < 8; c++) {
            uint32_t a[4][4], b[2][4];
            const uint32_t swA = (uint32_t)((((2 * c + hiA) & 8) |
                                            (((2 * c + hiA) & 7) ^ lx)) << 4) + cur;
            const uint32_t swB = (uint32_t)((((2 * c + hiB) & 8) |
                                            (((2 * c + hiB) & 7) ^ lx)) << 4) + cur;
#pragma unroll
            for (int mf = 0; mf < 4; mf++) ldsm4(a[mf], rA[mf] + swA);
#pragma unroll
            for (int h = 0; h < 2; h++) ldsm4(b[h], rB[h] + swB);
            if (c == 7) { cp_wait0(); __syncthreads(); }
#pragma unroll
            for (int mf = 0; mf < 4; mf++)
#pragma unroll
                for (int h = 0; h < 2; h++) {
                    mma8(acc[mf][2 * h],     a[mf], b[h][0], b[h][1]);
                    mma8(acc[mf][2 * h + 1], a[mf], b[h][2], b[h][3]);
                }
            if (more) {
                if (c == 0) {
#pragma unroll
                    for (int p = 0; p < 2; p++)
#pragma unroll
                        for (int j = 0; j < 2; j++)
                            wst[p][j] = *reinterpret_cast<const float4*>(bsrc[p] + ko + 32 * j);
                } else if (c == 2) {
#pragma unroll
                    for (int p = 0; p < 2; p++)
#pragma unroll
                        for (int j = 0; j < 2; j++)
                            *reinterpret_cast<uint4*>(smem + nxt + G2_B + oB[p][j]) = tf4(wst[p][j]);
#pragma unroll
                    for (int p = 0; p < 2; p++)
#pragma unroll
                        for (int j = 0; j < 2; j++)
                            wst[p][j] = *reinterpret_cast<const float4*>(bsrc[p + 2] + ko + 32 * j);
                } else if (c == 4) {
#pragma unroll
                    for (int p = 0; p < 2; p++)
#pragma unroll
                        for (int j = 0; j < 2; j++)
                            *reinterpret_cast<uint4*>(smem + nxt + G2_B + oB[p + 2][j]) = tf4(wst[p][j]);
                }
            }
        }
    }

    // ---- gated atomic scatter-combine ----
#pragma unroll
    for (int mf = 0; mf < 4; mf++) {
#pragma unroll
        for (int half = 0; half < 2; half++) {
            const int grow = row0 + wm + mf * 16 + half * 8 + lr;
            if (grow >= cnt) continue;
            const int   tok  = g_rowtok[e * CAP + grow];
            const float gate = g_rowgate[e * CAP + grow];
            float* orow = out + (size_t)tok * Kdim + k0;
#pragma unroll
            for (int nf = 0; nf < 4; nf++) {
                const int col = wn + nf * 8 + 2 * lc;
                atomicAdd(orow + col,     gate * acc[mf][nf][half * 2]);
                atomicAdd(orow + col + 1, gate * acc[mf][nf][half * 2 + 1]);
            }
        }
    }
}

// ---------------------------------------------------------------------------
// Launch
// ---------------------------------------------------------------------------
extern "C" void kernel_launch(void* const* d_in, const int* in_sizes, int n_in,
                              void* d_out, int out_size) {
    const float* X    = (const float*)d_in[0];
    const int*   fidx = (const int*)  d_in[1];
    const float* fg   = (const float*)d_in[2];
    const float* GW   = (const float*)d_in[3];
    const float* UW   = (const float*)d_in[4];
    const float* DW   = (const float*)d_in[5];
    float* out = (float*)d_out;

    cudaFuncSetAttribute(k_gemm1, cudaFuncAttributeMaxDynamicSharedMemorySize, G1_SMEM);
    cudaFuncSetAttribute(k_gemm2, cudaFuncAttributeMaxDynamicSharedMemorySize, G2_SMEM);

    k_prep<<<(Mtok * Kdim / 4 + 255) / 256, 256>>>(out, X);
    k_route<<<(RROWS + 255) / 256, 256>>>(fidx, fg);

    dim3 g1(Ndim / 128, CAP / 128, NE);   // 11 x 8 x 8
    k_gemm1<<<g1, 512, G1_SMEM>>>(GW, UW);

    dim3 g2(Kdim / 256, CAP / 128, NE);   // 8 x 8 x 8
    k_gemm2<<<g2, 512, G2_SMEM>>>(DW, out);
}

// round 15
// speedup vs baseline: 1.5553x; 1.5553x over previous
#include <cuda_runtime.h>
#include <cstdint>
#include <math.h>

// ---------------------------------------------------------------------------
// Problem constants
// ---------------------------------------------------------------------------
constexpr int Mtok  = 2048;
constexpr int Kdim  = 2048;
constexpr int Ndim  = 1408;
constexpr int NE    = 8;
constexpr int CAP   = 1024;
constexpr int RROWS = 4096;

// Scratch
__device__ int   g_count[NE];
__device__ int   g_rowtok[NE * CAP];
__device__ float g_rowgate[NE * CAP];
__device__ float g_xr[(size_t)Mtok * Kdim];      // tf32-rounded X
__device__ float g_h[(size_t)NE * CAP * Ndim];   // tf32-rounded activations

// ---------------------------------------------------------------------------
// Helpers
// ---------------------------------------------------------------------------
__device__ __forceinline__ uint32_t smem_u32(const void* p) {
    uint32_t a;
    asm("{ .reg .u64 t; cvta.to.shared.u64 t, %1; cvt.u32.u64 %0, t; }"
        : "=r"(a) : "l"(p));
    return a;
}
__device__ __forceinline__ uint32_t f2tf(float x) {
    uint32_t r; asm("cvt.rna.tf32.f32 %0, %1;" : "=r"(r) : "f"(x)); return r;
}
__device__ __forceinline__ uint4 tf4(float4 v) {
    return make_uint4(f2tf(v.x), f2tf(v.y), f2tf(v.z), f2tf(v.w));
}
__device__ __forceinline__ void mma8(float c[4], const uint32_t a[4],
                                     uint32_t b0, uint32_t b1) {
    asm volatile(
        "mma.sync.aligned.m16n8k8.row.col.f32.tf32.tf32.f32 "
        "{%0,%1,%2,%3}, {%4,%5,%6,%7}, {%8,%9}, {%0,%1,%2,%3};"
        : "+f"(c[0]), "+f"(c[1]), "+f"(c[2]), "+f"(c[3])
        : "r"(a[0]), "r"(a[1]), "r"(a[2]), "r"(a[3]), "r"(b0), "r"(b1));
}
__device__ __forceinline__ void ldsm4(uint32_t* r, uint32_t addr) {
    asm volatile("ldmatrix.sync.aligned.m8n8.x4.shared.b16 {%0,%1,%2,%3}, [%4];"
                 : "=r"(r[0]), "=r"(r[1]), "=r"(r[2]), "=r"(r[3]) : "r"(addr));
}
__device__ __forceinline__ void cp16(uint32_t dst, const void* src) {
    asm volatile("cp.async.cg.shared.global [%0], [%1], 16;"
                 :: "r"(dst), "l"(src));
}
__device__ __forceinline__ void cp_commit() {
    asm volatile("cp.async.commit_group;" ::: "memory");
}
__device__ __forceinline__ void cp_wait0() {
    asm volatile("cp.async.wait_group 0;" ::: "memory");
}
// 256B-row swizzle: 16 chunks of 16B; keep bit3, XOR low3 with row&7
__device__ __forceinline__ int sw256(int chunk, int row) {
    return ((chunk & 8) | ((chunk & 7) ^ (row & 7))) << 4;
}
// per-chunk ldsm swizzle offset for a lane (phase = 2*chunk + hi)
__device__ __forceinline__ uint32_t swz_ld(int phase, int lx) {
    return (uint32_t)(((phase & 8) | ((phase & 7) ^ lx)) << 4);
}

// ---------------------------------------------------------------------------
// Prep kernels
// ---------------------------------------------------------------------------
__global__ void k_prep(float* __restrict__ out, const float* __restrict__ X) {
    int idx = blockIdx.x * blockDim.x + threadIdx.x;
    if (idx < Mtok * Kdim / 4) {
        reinterpret_cast<float4*>(out)[idx] = make_float4(0.f, 0.f, 0.f, 0.f);
        reinterpret_cast<uint4*>(g_xr)[idx] =
            tf4(reinterpret_cast<const float4*>(X)[idx]);
    }
    if (idx < NE) g_count[idx] = 0;
}
__global__ void k_route(const int* __restrict__ flat_idx,
                        const float* __restrict__ flat_gate) {
    int r = blockIdx.x * blockDim.x + threadIdx.x;
    if (r >= RROWS) return;
    int e = flat_idx[r];
    if (e < 0 || e >= NE) return;
    int pos = atomicAdd(&g_count[e], 1);
    if (pos < CAP) {
        g_rowtok[e * CAP + pos]  = r >> 1;
        g_rowgate[e * CAP + pos] = flat_gate[r];
    }
}

// ---------------------------------------------------------------------------
// gemm1: gate+up. Block 128 rows x 128 n, BK=64, 256 threads, warps 2x4,
// warp tile 64 x 32 per matrix. B-frag chunk-ahead prefetch + a interleave.
// ---------------------------------------------------------------------------
constexpr int G1_A = 0, G1_BG = 32768, G1_BU = 65536, G1_STAGE = 98304;
constexpr int G1_SMEM = 2 * G1_STAGE;   // 192 KB

__global__ __launch_bounds__(256)
void k_gemm1(const float* __restrict__ GW, const float* __restrict__ UW) {
    extern __shared__ char smem[];
    const int e    = blockIdx.z;
    const int cnt  = min(g_count[e], CAP);
    const int row0 = blockIdx.y * 128;
    if (row0 >= cnt) return;
    const int n0  = blockIdx.x * 128;
    const int tid = threadIdx.x;
    const uint32_t sb = smem_u32(smem);

    // ---- staging ids: 8 thr/row, rows srow+32p, chunks {schk, schk+8} ----
    const int srow = tid >> 3, schk = tid & 7;
    int oA[4][2];
    const float* asrc[4];
    const float* gsrc[4];
    const float* usrc[4];
#pragma unroll
    for (int p = 0; p < 4; p++) {
        const int r = srow + 32 * p;
#pragma unroll
        for (int j = 0; j < 2; j++)
            oA[p][j] = r * 256 + sw256(schk + 8 * j, r);
        int tok = g_rowtok[e * CAP + row0 + r];
        asrc[p] = g_xr + (size_t)tok * Kdim + schk * 4;
        gsrc[p] = GW + ((size_t)e * Ndim + n0 + r) * Kdim + schk * 4;
        usrc[p] = UW + ((size_t)e * Ndim + n0 + r) * Kdim + schk * 4;
    }

    // ---- compute ids ----
    const int wid = tid >> 5, L = tid & 31;
    const int wm = (wid >> 2) * 64, wn = (wid & 3) * 32;
    const int lr = L >> 2, lc = L & 3;
    const int rowoffA = ((L >> 3) & 1) * 8 + (L & 7);
    const int hiA = L >> 4;
    const int rowoffB = ((L >> 4) & 1) * 8 + (L & 7);
    const int hiB = (L >> 3) & 1;
    const int lx = L & 7;
    uint32_t rA[4], rBg[2], rBu[2];
#pragma unroll
    for (int mf = 0; mf < 4; mf++)
        rA[mf] = sb + G1_A + (wm + mf * 16 + rowoffA) * 256;
#pragma unroll
    for (int h = 0; h < 2; h++) {
        rBg[h] = sb + G1_BG + (wn + h * 16 + rowoffB) * 256;
        rBu[h] = sb + G1_BU + (wn + h * 16 + rowoffB) * 256;
    }

    float accG[4][4][4], accU[4][4][4];
#pragma unroll
    for (int mf = 0; mf < 4; mf++)
#pragma unroll
        for (int nf = 0; nf < 4; nf++)
#pragma unroll
            for (int q = 0; q < 4; q++) { accG[mf][nf][q] = 0.f; accU[mf][nf][q] = 0.f; }

    // ---- prologue: stage 0 ----
#pragma unroll
    for (int p = 0; p < 4; p++)
#pragma unroll
        for (int j = 0; j < 2; j++)
            cp16(sb + G1_A + oA[p][j], asrc[p] + 32 * j);
    cp_commit();
    {
        float4 w[4][2];
#pragma unroll
        for (int p = 0; p < 4; p++)
#pragma unroll
            for (int j = 0; j < 2; j++)
                w[p][j] = *reinterpret_cast<const float4*>(gsrc[p] + 32 * j);
#pragma unroll
        for (int p = 0; p < 4; p++)
#pragma unroll
            for (int j = 0; j < 2; j++)
                *reinterpret_cast<uint4*>(smem + G1_BG + oA[p][j]) = tf4(w[p][j]);
#pragma unroll
        for (int p = 0; p < 4; p++)
#pragma unroll
            for (int j = 0; j < 2; j++)
                w[p][j] = *reinterpret_cast<const float4*>(usrc[p] + 32 * j);
#pragma unroll
        for (int p = 0; p < 4; p++)
#pragma unroll
            for (int j = 0; j < 2; j++)
                *reinterpret_cast<uint4*>(smem + G1_BU + oA[p][j]) = tf4(w[p][j]);
    }
    cp_wait0();
    __syncthreads();

    // double-banked B fragments; initial prefetch: stage 0, chunk 0, bank 0
    uint32_t bg[2][2][4], bu[2][2][4];
    {
        const uint32_t swB = swz_ld(hiB, lx);
#pragma unroll
        for (int h = 0; h < 2; h++) {
            ldsm4(bg[0][h], rBg[h] + swB);
            ldsm4(bu[0][h], rBu[h] + swB);
        }
    }

    const int KT = Kdim / 64;   // 32 stages
    float4 wst[4][2];
    for (int kt = 0; kt < KT; ++kt) {
        const int cur = (kt & 1) * G1_STAGE;
        const int nxt = ((kt + 1) & 1) * G1_STAGE;
        const bool more = (kt + 1 < KT);
        const int ko = (kt + 1) * 64;
        if (more) {
#pragma unroll
            for (int p = 0; p < 4; p++)
#pragma unroll
                for (int j = 0; j < 2; j++)
                    cp16(sb + nxt + G1_A + oA[p][j], asrc[p] + ko + 32 * j);
            cp_commit();
        }
#pragma unroll
        for (int c = 0; c < 8; c++) {
            const int pb = c & 1, nb = 1 - pb;
            const uint32_t swA = swz_ld(2 * c + hiA, lx) + cur;
            uint32_t a[4][4];
            ldsm4(a[0], rA[0] + swA);
            if (c < 7) {
                const uint32_t swBn = swz_ld(2 * (c + 1) + hiB, lx) + cur;
                // mf = 0 : load a1, mma a0
                ldsm4(a[1], rA[1] + swA);
                mma8(accG[0][0], a[0], bg[pb][0][0], bg[pb][0][1]);
                mma8(accG[0][1], a[0], bg[pb][0][2], bg[pb][0][3]);
                mma8(accG[0][2], a[0], bg[pb][1][0], bg[pb][1][1]);
                mma8(accG[0][3], a[0], bg[pb][1][2], bg[pb][1][3]);
                mma8(accU[0][0], a[0], bu[pb][0][0], bu[pb][0][1]);
                mma8(accU[0][1], a[0], bu[pb][0][2], bu[pb][0][3]);
                mma8(accU[0][2], a[0], bu[pb][1][0], bu[pb][1][1]);
                mma8(accU[0][3], a[0], bu[pb][1][2], bu[pb][1][3]);
                // mf = 1 : load a2 + prefetch next-chunk B, mma a1
                ldsm4(a[2], rA[2] + swA);
#pragma unroll
                for (int h = 0; h < 2; h++) {
                    ldsm4(bg[nb][h], rBg[h] + swBn);
                    ldsm4(bu[nb][h], rBu[h] + swBn);
                }
                mma8(accG[1][0], a[1], bg[pb][0][0], bg[pb][0][1]);
                mma8(accG[1][1], a[1], bg[pb][0][2], bg[pb][0][3]);
                mma8(accG[1][2], a[1], bg[pb][1][0], bg[pb][1][1]);
                mma8(accG[1][3], a[1], bg[pb][1][2], bg[pb][1][3]);
                mma8(accU[1][0], a[1], bu[pb][0][0], bu[pb][0][1]);
                mma8(accU[1][1], a[1], bu[pb][0][2], bu[pb][0][3]);
                mma8(accU[1][2], a[1], bu[pb][1][0], bu[pb][1][1]);
                mma8(accU[1][3], a[1], bu[pb][1][2], bu[pb][1][3]);
                // mf = 2 : load a3, mma a2
                ldsm4(a[3], rA[3] + swA);
                mma8(accG[2][0], a[2], bg[pb][0][0], bg[pb][0][1]);
                mma8(accG[2][1], a[2], bg[pb][0][2], bg[pb][0][3]);
                mma8(accG[2][2], a[2], bg[pb][1][0], bg[pb][1][1]);
                mma8(accG[2][3], a[2], bg[pb][1][2], bg[pb][1][3]);
                mma8(accU[2][0], a[2], bu[pb][0][0], bu[pb][0][1]);
                mma8(accU[2][1], a[2], bu[pb][0][2], bu[pb][0][3]);
                mma8(accU[2][2], a[2], bu[pb][1][0], bu[pb][1][1]);
                mma8(accU[2][3], a[2], bu[pb][1][2], bu[pb][1][3]);
                // mf = 3 : mma a3
                mma8(accG[3][0], a[3], bg[pb][0][0], bg[pb][0][1]);
                mma8(accG[3][1], a[3], bg[pb][0][2], bg[pb][0][3]);
                mma8(accG[3][2], a[3], bg[pb][1][0], bg[pb][1][1]);
                mma8(accG[3][3], a[3], bg[pb][1][2], bg[pb][1][3]);
                mma8(accU[3][0], a[3], bu[pb][0][0], bu[pb][0][1]);
                mma8(accU[3][1], a[3], bu[pb][0][2], bu[pb][0][3]);
                mma8(accU[3][2], a[3], bu[pb][1][0], bu[pb][1][1]);
                mma8(accU[3][3], a[3], bu[pb][1][2], bu[pb][1][3]);
            } else {
                // last chunk: finish all cur reads, barrier, prefetch from nxt
                ldsm4(a[1], rA[1] + swA);
                ldsm4(a[2], rA[2] + swA);
                ldsm4(a[3], rA[3] + swA);
                if (more) {
                    cp_wait0();
                    __syncthreads();
                    const uint32_t swBn = swz_ld(hiB, lx) + nxt;
#pragma unroll
                    for (int h = 0; h < 2; h++) {
                        ldsm4(bg[nb][h], rBg[h] + swBn);
                        ldsm4(bu[nb][h], rBu[h] + swBn);
                    }
                }
#pragma unroll
                for (int mf = 0; mf < 4; mf++) {
                    mma8(accG[mf][0], a[mf], bg[pb][0][0], bg[pb][0][1]);
                    mma8(accG[mf][1], a[mf], bg[pb][0][2], bg[pb][0][3]);
                    mma8(accG[mf][2], a[mf], bg[pb][1][0], bg[pb][1][1]);
                    mma8(accG[mf][3], a[mf], bg[pb][1][2], bg[pb][1][3]);
                    mma8(accU[mf][0], a[mf], bu[pb][0][0], bu[pb][0][1]);
                    mma8(accU[mf][1], a[mf], bu[pb][0][2], bu[pb][0][3]);
                    mma8(accU[mf][2], a[mf], bu[pb][1][0], bu[pb][1][1]);
                    mma8(accU[mf][3], a[mf], bu[pb][1][2], bu[pb][1][3]);
                }
            }
            // weight staging for stage kt+1 (all writes pre-barrier)
            if (more) {
                if (c == 0) {
#pragma unroll
                    for (int p = 0; p < 4; p++)
#pragma unroll
                        for (int j = 0; j < 2; j++)
                            wst[p][j] = *reinterpret_cast<const float4*>(gsrc[p] + ko + 32 * j);
                } else if (c == 2) {
#pragma unroll
                    for (int p = 0; p < 4; p++)
#pragma unroll
                        for (int j = 0; j < 2; j++)
                            *reinterpret_cast<uint4*>(smem + nxt + G1_BG + oA[p][j]) = tf4(wst[p][j]);
#pragma unroll
                    for (int p = 0; p < 4; p++)
#pragma unroll
                        for (int j = 0; j < 2; j++)
                            wst[p][j] = *reinterpret_cast<const float4*>(usrc[p] + ko + 32 * j);
                } else if (c == 4) {
#pragma unroll
                    for (int p = 0; p < 4; p++)
#pragma unroll
                        for (int j = 0; j < 2; j++)
                            *reinterpret_cast<uint4*>(smem + nxt + G1_BU + oA[p][j]) = tf4(wst[p][j]);
                }
            }
        }
    }

    // ---- SwiGLU epilogue -> g_h (tf32-rounded) ----
#pragma unroll
    for (int mf = 0; mf < 4; mf++) {
#pragma unroll
        for (int half = 0; half < 2; half++) {
            const int grow = row0 + wm + mf * 16 + half * 8 + lr;
            if (grow >= cnt) continue;
            float* hrow = g_h + ((size_t)e * CAP + grow) * Ndim;
#pragma unroll
            for (int nf = 0; nf < 4; nf++) {
                const int col = n0 + wn + nf * 8 + 2 * lc;
                float2 o;
#pragma unroll
                for (int q = 0; q < 2; q++) {
                    float g = fminf(accG[mf][nf][half * 2 + q], 10.f);
                    float u = fminf(fmaxf(accU[mf][nf][half * 2 + q], -10.f), 10.f);
                    float h = (g / (1.f + expf(-g))) * u;
                    (&o.x)[q] = __uint_as_float(f2tf(h));
                }
                *reinterpret_cast<float2*>(hrow + col) = o;
            }
        }
    }
}

// ---------------------------------------------------------------------------
// gemm2: down. Block 128 rows x 256 k-out, BK=64 over N, 256 threads,
// warps 2x4, warp tile 64x64. Same prefetch structure.
// ---------------------------------------------------------------------------
constexpr int G2_A = 0, G2_B = 32768, G2_STAGE = 98304;
constexpr int G2_SMEM = 2 * G2_STAGE;   // 192 KB

__global__ __launch_bounds__(256)
void k_gemm2(const float* __restrict__ DW, float* __restrict__ out) {
    extern __shared__ char smem[];
    const int e    = blockIdx.z;
    const int cnt  = min(g_count[e], CAP);
    const int row0 = blockIdx.y * 128;
    if (row0 >= cnt) return;
    const int k0  = blockIdx.x * 256;
    const int tid = threadIdx.x;
    const uint32_t sb = smem_u32(smem);

    const int srow = tid >> 3, schk = tid & 7;
    int oA[4][2], oB[8][2];
    const float* ha[4];
    const float* bsrc[8];
#pragma unroll
    for (int p = 0; p < 4; p++) {
        const int r = srow + 32 * p;
#pragma unroll
        for (int j = 0; j < 2; j++) oA[p][j] = r * 256 + sw256(schk + 8 * j, r);
        ha[p] = g_h + ((size_t)e * CAP + row0 + r) * Ndim + schk * 4;
    }
#pragma unroll
    for (int p = 0; p < 8; p++) {
        const int r = srow + 32 * p;
#pragma unroll
        for (int j = 0; j < 2; j++) oB[p][j] = r * 256 + sw256(schk + 8 * j, r);
        bsrc[p] = DW + ((size_t)e * Kdim + k0 + r) * Ndim + schk * 4;
    }

    const int wid = tid >> 5, L = tid & 31;
    const int wm = (wid >> 2) * 64, wn = (wid & 3) * 64;
    const int lr = L >> 2, lc = L & 3;
    const int rowoffA = ((L >> 3) & 1) * 8 + (L & 7);
    const int hiA = L >> 4;
    const int rowoffB = ((L >> 4) & 1) * 8 + (L & 7);
    const int hiB = (L >> 3) & 1;
    const int lx = L & 7;
    uint32_t rA[4], rB[4];
#pragma unroll
    for (int mf = 0; mf < 4; mf++)
        rA[mf] = sb + G2_A + (wm + mf * 16 + rowoffA) * 256;
#pragma unroll
    for (int h = 0; h < 4; h++)
        rB[h] = sb + G2_B + (wn + h * 16 + rowoffB) * 256;

    float acc[4][8][4];
#pragma unroll
    for (int mf = 0; mf < 4; mf++)
#pragma unroll
        for (int nf = 0; nf < 8; nf++)
#pragma unroll
            for (int q = 0; q < 4; q++) acc[mf][nf][q] = 0.f;

    // prologue stage 0
#pragma unroll
    for (int p = 0; p < 4; p++)
#pragma unroll
        for (int j = 0; j < 2; j++)
            cp16(sb + G2_A + oA[p][j], ha[p] + 32 * j);
    cp_commit();
    {
        float4 w;
#pragma unroll
        for (int p = 0; p < 8; p++)
#pragma unroll
            for (int j = 0; j < 2; j++) {
                w = *reinterpret_cast<const float4*>(bsrc[p] + 32 * j);
                *reinterpret_cast<uint4*>(smem + G2_B + oB[p][j]) = tf4(w);
            }
    }
    cp_wait0();
    __syncthreads();

    // double-banked B fragments; initial prefetch: stage 0 chunk 0, bank 0
    uint32_t b[2][4][4];
    {
        const uint32_t swB = swz_ld(hiB, lx);
#pragma unroll
        for (int h = 0; h < 4; h++) ldsm4(b[0][h], rB[h] + swB);
    }

    const int KT = Ndim / 64;   // 22 stages
    float4 wst[4][2];
    for (int kt = 0; kt < KT; ++kt) {
        const int cur = (kt & 1) * G2_STAGE;
        const int nxt = ((kt + 1) & 1) * G2_STAGE;
        const bool more = (kt + 1 < KT);
        const int ko = (kt + 1) * 64;
        if (more) {
#pragma unroll
            for (int p = 0; p < 4; p++)
#pragma unroll
                for (int j = 0; j < 2; j++)
                    cp16(sb + nxt + G2_A + oA[p][j], ha[p] + ko + 32 * j);
            cp_commit();
        }
#pragma unroll
        for (int c = 0; c < 8; c++) {
            const int pb = c & 1, nb = 1 - pb;
            const uint32_t swA = swz_ld(2 * c + hiA, lx) + cur;
            uint32_t a[4][4];
            ldsm4(a[0], rA[0] + swA);
            if (c < 7) {
                const uint32_t swBn = swz_ld(2 * (c + 1) + hiB, lx) + cur;
                // mf = 0
                ldsm4(a[1], rA[1] + swA);
#pragma unroll
                for (int h = 0; h < 4; h++) {
                    mma8(acc[0][2 * h],     a[0], b[pb][h][0], b[pb][h][1]);
                    mma8(acc[0][2 * h + 1], a[0], b[pb][h][2], b[pb][h][3]);
                }
                // mf = 1 + next-chunk B prefetch
                ldsm4(a[2], rA[2] + swA);
#pragma unroll
                for (int h = 0; h < 4; h++) ldsm4(b[nb][h], rB[h] + swBn);
#pragma unroll
                for (int h = 0; h < 4; h++) {
                    mma8(acc[1][2 * h],     a[1], b[pb][h][0], b[pb][h][1]);
                    mma8(acc[1][2 * h + 1], a[1], b[pb][h][2], b[pb][h][3]);
                }
                // mf = 2
                ldsm4(a[3], rA[3] + swA);
#pragma unroll
                for (int h = 0; h < 4; h++) {
                    mma8(acc[2][2 * h],     a[2], b[pb][h][0], b[pb][h][1]);
                    mma8(acc[2][2 * h + 1], a[2], b[pb][h][2], b[pb][h][3]);
                }
                // mf = 3
#pragma unroll
                for (int h = 0; h < 4; h++) {
                    mma8(acc[3][2 * h],     a[3], b[pb][h][0], b[pb][h][1]);
                    mma8(acc[3][2 * h + 1], a[3], b[pb][h][2], b[pb][h][3]);
                }
            } else {
                ldsm4(a[1], rA[1] + swA);
                ldsm4(a[2], rA[2] + swA);
                ldsm4(a[3], rA[3] + swA);
                if (more) {
                    cp_wait0();
                    __syncthreads();
                    const uint32_t swBn = swz_ld(hiB, lx) + nxt;
#pragma unroll
                    for (int h = 0; h < 4; h++) ldsm4(b[nb][h], rB[h] + swBn);
                }
#pragma unroll
                for (int mf = 0; mf < 4; mf++)
#pragma unroll
                    for (int h = 0; h < 4; h++) {
                        mma8(acc[mf][2 * h],     a[mf], b[pb][h][0], b[pb][h][1]);
                        mma8(acc[mf][2 * h + 1], a[mf], b[pb][h][2], b[pb][h][3]);
                    }
            }
            if (more) {
                if (c == 0) {
#pragma unroll
                    for (int p = 0; p < 4; p++)
#pragma unroll
                        for (int j = 0; j < 2; j++)
                            wst[p][j] = *reinterpret_cast<const float4*>(bsrc[p] + ko + 32 * j);
                } else if (c == 2) {
#pragma unroll
                    for (int p = 0; p < 4; p++)
#pragma unroll
                        for (int j = 0; j < 2; j++)
                            *reinterpret_cast<uint4*>(smem + nxt + G2_B + oB[p][j]) = tf4(wst[p][j]);
#pragma unroll
                    for (int p = 0; p < 4; p++)
#pragma unroll
                        for (int j = 0; j < 2; j++)
                            wst[p][j] = *reinterpret_cast<const float4*>(bsrc[p + 4] + ko + 32 * j);
                } else if (c == 4) {
#pragma unroll
                    for (int p = 0; p < 4; p++)
#pragma unroll
                        for (int j = 0; j < 2; j++)
                            *reinterpret_cast<uint4*>(smem + nxt + G2_B + oB[p + 4][j]) = tf4(wst[p][j]);
                }
            }
        }
    }

    // ---- gated atomic scatter-combine ----
#pragma unroll
    for (int mf = 0; mf < 4; mf++) {
#pragma unroll
        for (int half = 0; half < 2; half++) {
            const int grow = row0 + wm + mf * 16 + half * 8 + lr;
            if (grow >= cnt) continue;
            const int   tok  = g_rowtok[e * CAP + grow];
            const float gate = g_rowgate[e * CAP + grow];
            float* orow = out + (size_t)tok * Kdim + k0;
#pragma unroll
            for (int nf = 0; nf < 8; nf++) {
                const int col = wn + nf * 8 + 2 * lc;
                atomicAdd(orow + col,     gate * acc[mf][nf][half * 2]);
                atomicAdd(orow + col + 1, gate * acc[mf][nf][half * 2 + 1]);
            }
        }
    }
}

// ---------------------------------------------------------------------------
// Launch
// ---------------------------------------------------------------------------
extern "C" void kernel_launch(void* const* d_in, const int* in_sizes, int n_in,
                              void* d_out, int out_size) {
    const float* X    = (const float*)d_in[0];
    const int*   fidx = (const int*)  d_in[1];
    const float* fg   = (const float*)d_in[2];
    const float* GW   = (const float*)d_in[3];
    const float* UW   = (const float*)d_in[4];
    const float* DW   = (const float*)d_in[5];
    float* out = (float*)d_out;

    cudaFuncSetAttribute(k_gemm1, cudaFuncAttributeMaxDynamicSharedMemorySize, G1_SMEM);
    cudaFuncSetAttribute(k_gemm2, cudaFuncAttributeMaxDynamicSharedMemorySize, G2_SMEM);

    k_prep<<<(Mtok * Kdim / 4 + 255) / 256, 256>>>(out, X);
    k_route<<<(RROWS + 255) / 256, 256>>>(fidx, fg);

    dim3 g1(Ndim / 128, CAP / 128, NE);   // 11 x 8 x 8
    k_gemm1<<<g1, 256, G1_SMEM>>>(GW, UW);

    dim3 g2(Kdim / 256, CAP / 128, NE);   // 8 x 8 x 8
    k_gemm2<<<g2, 256, G2_SMEM>>>(DW, out);
}

// round 16
// speedup vs baseline: 2.2542x; 1.4494x over previous
#include <cuda_runtime.h>
#include <cuda_fp16.h>
#include <cstdint>
#include <math.h>

// ---------------------------------------------------------------------------
// Problem constants
// ---------------------------------------------------------------------------
constexpr int Mtok  = 2048;
constexpr int Kdim  = 2048;
constexpr int Ndim  = 1408;
constexpr int NE    = 8;
constexpr int CAP   = 1024;
constexpr int RROWS = 4096;

// Scratch
__device__ int    g_count[NE];
__device__ int    g_rowtok[NE * CAP];
__device__ float  g_rowgate[NE * CAP];
__device__ __half g_xh[(size_t)Mtok * Kdim];      // fp16 X
__device__ __half g_h[(size_t)NE * CAP * Ndim];   // fp16 activations

// ---------------------------------------------------------------------------
// Helpers
// ---------------------------------------------------------------------------
__device__ __forceinline__ uint32_t smem_u32(const void* p) {
    uint32_t a;
    asm("{ .reg .u64 t; cvta.to.shared.u64 t, %1; cvt.u32.u64 %0, t; }"
        : "=r"(a) : "l"(p));
    return a;
}
// pack two floats into half2 (x -> low, y -> high), round-to-nearest-even
__device__ __forceinline__ uint32_t f2h2(float x, float y) {
    uint32_t r;
    asm("cvt.rn.f16x2.f32 %0, %1, %2;" : "=r"(r) : "f"(y), "f"(x));
    return r;
}
// float4 -> 4 packed half2 words? No: 4 floats -> 2 words. 8 floats -> uint4.
__device__ __forceinline__ uint4 h16(float4 a, float4 b) {
    return make_uint4(f2h2(a.x, a.y), f2h2(a.z, a.w),
                      f2h2(b.x, b.y), f2h2(b.z, b.w));
}
__device__ __forceinline__ void mma16(float c[4], const uint32_t a[4],
                                      uint32_t b0, uint32_t b1) {
    asm volatile(
        "mma.sync.aligned.m16n8k16.row.col.f32.f16.f16.f32 "
        "{%0,%1,%2,%3}, {%4,%5,%6,%7}, {%8,%9}, {%0,%1,%2,%3};"
        : "+f"(c[0]), "+f"(c[1]), "+f"(c[2]), "+f"(c[3])
        : "r"(a[0]), "r"(a[1]), "r"(a[2]), "r"(a[3]), "r"(b0), "r"(b1));
}
__device__ __forceinline__ void ldsm4(uint32_t* r, uint32_t addr) {
    asm volatile("ldmatrix.sync.aligned.m8n8.x4.shared.b16 {%0,%1,%2,%3}, [%4];"
                 : "=r"(r[0]), "=r"(r[1]), "=r"(r[2]), "=r"(r[3]) : "r"(addr));
}
__device__ __forceinline__ void cp16(uint32_t dst, const void* src) {
    asm volatile("cp.async.cg.shared.global [%0], [%1], 16;"
                 :: "r"(dst), "l"(src));
}
__device__ __forceinline__ void cp_commit() {
    asm volatile("cp.async.commit_group;" ::: "memory");
}
__device__ __forceinline__ void cp_wait0() {
    asm volatile("cp.async.wait_group 0;" ::: "memory");
}
// 128B-row swizzle: 8 chunks of 16B; XOR chunk with row&7
__device__ __forceinline__ int sw128(int chunk, int row) {
    return ((chunk ^ (row & 7))) << 4;
}

// ---------------------------------------------------------------------------
// Prep kernels: zero out, convert X -> fp16, route
// ---------------------------------------------------------------------------
__global__ void k_prep(float* __restrict__ out, const float* __restrict__ X) {
    int idx = blockIdx.x * blockDim.x + threadIdx.x;
    if (idx < Mtok * Kdim / 4)
        reinterpret_cast<float4*>(out)[idx] = make_float4(0.f, 0.f, 0.f, 0.f);
    if (idx < Mtok * Kdim / 8) {
        float4 a = reinterpret_cast<const float4*>(X)[2 * idx];
        float4 b = reinterpret_cast<const float4*>(X)[2 * idx + 1];
        reinterpret_cast<uint4*>(g_xh)[idx] = h16(a, b);
    }
    if (idx < NE) g_count[idx] = 0;
}
__global__ void k_route(const int* __restrict__ flat_idx,
                        const float* __restrict__ flat_gate) {
    int r = blockIdx.x * blockDim.x + threadIdx.x;
    if (r >= RROWS) return;
    int e = flat_idx[r];
    if (e < 0 || e >= NE) return;
    int pos = atomicAdd(&g_count[e], 1);
    if (pos < CAP) {
        g_rowtok[e * CAP + pos]  = r >> 1;
        g_rowgate[e * CAP + pos] = flat_gate[r];
    }
}

// ---------------------------------------------------------------------------
// gemm1: gate+up fp16. Block 128 rows x 128 n, BK=64 (4 k16-chunks/stage).
// 256 thr, warps 2x4; warp tile 64 x 32 per matrix. Hidden stage barrier.
// ---------------------------------------------------------------------------
constexpr int G1_A = 0, G1_BG = 16384, G1_BU = 32768, G1_STAGE = 49152;
constexpr int G1_SMEM = 2 * G1_STAGE;   // 96 KB

__global__ __launch_bounds__(256)
void k_gemm1(const float* __restrict__ GW, const float* __restrict__ UW) {
    extern __shared__ char smem[];
    const int e    = blockIdx.z;
    const int cnt  = min(g_count[e], CAP);
    const int row0 = blockIdx.y * 128;
    if (row0 >= cnt) return;
    const int n0  = blockIdx.x * 128;
    const int tid = threadIdx.x;
    const uint32_t sb = smem_u32(smem);

    // ---- staging ids: 8 thr/row; thread handles chunk schk of rows srow+32p
    const int srow = tid >> 3, schk = tid & 7;
    int oT[4];                       // tile-relative smem offsets (A/G/U rows)
    const __half* asrc[4];
    const float* gsrc[4];
    const float* usrc[4];
#pragma unroll
    for (int p = 0; p < 4; p++) {
        const int r = srow + 32 * p;
        oT[p] = r * 128 + sw128(schk, r);
        int tok = g_rowtok[e * CAP + row0 + r];
        asrc[p] = g_xh + (size_t)tok * Kdim + schk * 8;
        gsrc[p] = GW + ((size_t)e * Ndim + n0 + r) * Kdim + schk * 8;
        usrc[p] = UW + ((size_t)e * Ndim + n0 + r) * Kdim + schk * 8;
    }

    // ---- compute ids ----
    const int wid = tid >> 5, L = tid & 31;
    const int wm = (wid >> 2) * 64, wn = (wid & 3) * 32;
    const int lr = L >> 2, lc = L & 3;
    const int rowoffA = ((L >> 3) & 1) * 8 + (L & 7);
    const int hiA = L >> 4;
    const int rowoffB = ((L >> 4) & 1) * 8 + (L & 7);
    const int hiB = (L >> 3) & 1;
    const int lx = L & 7;
    uint32_t rA[4], rBg[2], rBu[2];
#pragma unroll
    for (int mf = 0; mf < 4; mf++)
        rA[mf] = sb + G1_A + (wm + mf * 16 + rowoffA) * 128;
#pragma unroll
    for (int h = 0; h < 2; h++) {
        rBg[h] = sb + G1_BG + (wn + h * 16 + rowoffB) * 128;
        rBu[h] = sb + G1_BU + (wn + h * 16 + rowoffB) * 128;
    }

    float accG[4][4][4], accU[4][4][4];
#pragma unroll
    for (int mf = 0; mf < 4; mf++)
#pragma unroll
        for (int nf = 0; nf < 4; nf++)
#pragma unroll
            for (int q = 0; q < 4; q++) { accG[mf][nf][q] = 0.f; accU[mf][nf][q] = 0.f; }

    // ---- prologue: stage 0 ----
#pragma unroll
    for (int p = 0; p < 4; p++) cp16(sb + G1_A + oT[p], asrc[p]);
    cp_commit();
    {
        float4 wa[4], wb[4];
#pragma unroll
        for (int p = 0; p < 4; p++) {
            wa[p] = *reinterpret_cast<const float4*>(gsrc[p]);
            wb[p] = *reinterpret_cast<const float4*>(gsrc[p] + 4);
        }
#pragma unroll
        for (int p = 0; p < 4; p++)
            *reinterpret_cast<uint4*>(smem + G1_BG + oT[p]) = h16(wa[p], wb[p]);
#pragma unroll
        for (int p = 0; p < 4; p++) {
            wa[p] = *reinterpret_cast<const float4*>(usrc[p]);
            wb[p] = *reinterpret_cast<const float4*>(usrc[p] + 4);
        }
#pragma unroll
        for (int p = 0; p < 4; p++)
            *reinterpret_cast<uint4*>(smem + G1_BU + oT[p]) = h16(wa[p], wb[p]);
    }
    cp_wait0();
    __syncthreads();

    const int KT = Kdim / 64;   // 32 stages
    float4 wga[4], wgb[4];
    for (int kt = 0; kt < KT; ++kt) {
        const int cur = (kt & 1) * G1_STAGE;
        const int nxt = ((kt + 1) & 1) * G1_STAGE;
        const bool more = (kt + 1 < KT);
        const int ko = (kt + 1) * 64;   // halves / floats offset
        if (more) {
#pragma unroll
            for (int p = 0; p < 4; p++)
                cp16(sb + nxt + G1_A + oT[p], asrc[p] + ko);
            cp_commit();
        }
#pragma unroll
        for (int c = 0; c < 4; c++) {
            uint32_t a[4][4], bg[2][4], bu[2][4];
            const uint32_t swA = (uint32_t)(((2 * c + hiA) ^ lx) << 4) + cur;
            const uint32_t swB = (uint32_t)(((2 * c + hiB) ^ lx) << 4) + cur;
#pragma unroll
            for (int mf = 0; mf < 4; mf++) ldsm4(a[mf], rA[mf] + swA);
#pragma unroll
            for (int h = 0; h < 2; h++) {
                ldsm4(bg[h], rBg[h] + swB);
                ldsm4(bu[h], rBu[h] + swB);
            }
            // hidden stage barrier: all reads of `cur` done; mma(3) from regs
            if (c == 3) { cp_wait0(); __syncthreads(); }
#pragma unroll
            for (int mf = 0; mf < 4; mf++)
#pragma unroll
                for (int h = 0; h < 2; h++) {
                    mma16(accG[mf][2 * h],     a[mf], bg[h][0], bg[h][1]);
                    mma16(accG[mf][2 * h + 1], a[mf], bg[h][2], bg[h][3]);
                    mma16(accU[mf][2 * h],     a[mf], bu[h][0], bu[h][1]);
                    mma16(accU[mf][2 * h + 1], a[mf], bu[h][2], bu[h][3]);
                }
            // weight staging for stage kt+1 (all writes pre-barrier)
            if (more) {
                if (c == 0) {
#pragma unroll
                    for (int p = 0; p < 4; p++) {
                        wga[p] = *reinterpret_cast<const float4*>(gsrc[p] + ko);
                        wgb[p] = *reinterpret_cast<const float4*>(gsrc[p] + ko + 4);
                    }
                } else if (c == 1) {
#pragma unroll
                    for (int p = 0; p < 4; p++)
                        *reinterpret_cast<uint4*>(smem + nxt + G1_BG + oT[p]) = h16(wga[p], wgb[p]);
#pragma unroll
                    for (int p = 0; p < 4; p++) {
                        wga[p] = *reinterpret_cast<const float4*>(usrc[p] + ko);
                        wgb[p] = *reinterpret_cast<const float4*>(usrc[p] + ko + 4);
                    }
                } else if (c == 2) {
#pragma unroll
                    for (int p = 0; p < 4; p++)
                        *reinterpret_cast<uint4*>(smem + nxt + G1_BU + oT[p]) = h16(wga[p], wgb[p]);
                }
            }
        }
    }

    // ---- SwiGLU epilogue -> g_h (fp16) ----
#pragma unroll
    for (int mf = 0; mf < 4; mf++) {
#pragma unroll
        for (int half = 0; half < 2; half++) {
            const int grow = row0 + wm + mf * 16 + half * 8 + lr;
            if (grow >= cnt) continue;
            __half* hrow = g_h + ((size_t)e * CAP + grow) * Ndim;
#pragma unroll
            for (int nf = 0; nf < 4; nf++) {
                const int col = n0 + wn + nf * 8 + 2 * lc;
                float hv[2];
#pragma unroll
                for (int q = 0; q < 2; q++) {
                    float g = fminf(accG[mf][nf][half * 2 + q], 10.f);
                    float u = fminf(fmaxf(accU[mf][nf][half * 2 + q], -10.f), 10.f);
                    hv[q] = (g / (1.f + expf(-g))) * u;
                }
                *reinterpret_cast<uint32_t*>(hrow + col) = f2h2(hv[0], hv[1]);
            }
        }
    }
}

// ---------------------------------------------------------------------------
// gemm2: down fp16. Block 128 rows x 256 k-out, BK=64 over N (4 k16-chunks).
// 256 thr, warps 2x4; warp tile 64x64. Hidden stage barrier.
// ---------------------------------------------------------------------------
constexpr int G2_A = 0, G2_B = 16384, G2_STAGE = 49152;
constexpr int G2_SMEM = 2 * G2_STAGE;   // 96 KB

__global__ __launch_bounds__(256)
void k_gemm2(const float* __restrict__ DW, float* __restrict__ out) {
    extern __shared__ char smem[];
    const int e    = blockIdx.z;
    const int cnt  = min(g_count[e], CAP);
    const int row0 = blockIdx.y * 128;
    if (row0 >= cnt) return;
    const int k0  = blockIdx.x * 256;
    const int tid = threadIdx.x;
    const uint32_t sb = smem_u32(smem);

    const int srow = tid >> 3, schk = tid & 7;
    int oA[4], oB[8];
    const __half* ha[4];
    const float* bsrc[8];
#pragma unroll
    for (int p = 0; p < 4; p++) {
        const int r = srow + 32 * p;
        oA[p] = r * 128 + sw128(schk, r);
        ha[p] = g_h + ((size_t)e * CAP + row0 + r) * Ndim + schk * 8;
    }
#pragma unroll
    for (int p = 0; p < 8; p++) {
        const int r = srow + 32 * p;
        oB[p] = r * 128 + sw128(schk, r);
        bsrc[p] = DW + ((size_t)e * Kdim + k0 + r) * Ndim + schk * 8;
    }

    const int wid = tid >> 5, L = tid & 31;
    const int wm = (wid >> 2) * 64, wn = (wid & 3) * 64;
    const int lr = L >> 2, lc = L & 3;
    const int rowoffA = ((L >> 3) & 1) * 8 + (L & 7);
    const int hiA = L >> 4;
    const int rowoffB = ((L >> 4) & 1) * 8 + (L & 7);
    const int hiB = (L >> 3) & 1;
    const int lx = L & 7;
    uint32_t rA[4], rB[4];
#pragma unroll
    for (int mf = 0; mf < 4; mf++)
        rA[mf] = sb + G2_A + (wm + mf * 16 + rowoffA) * 128;
#pragma unroll
    for (int h = 0; h < 4; h++)
        rB[h] = sb + G2_B + (wn + h * 16 + rowoffB) * 128;

    float acc[4][8][4];
#pragma unroll
    for (int mf = 0; mf < 4; mf++)
#pragma unroll
        for (int nf = 0; nf < 8; nf++)
#pragma unroll
            for (int q = 0; q < 4; q++) acc[mf][nf][q] = 0.f;

    // prologue stage 0
#pragma unroll
    for (int p = 0; p < 4; p++) cp16(sb + G2_A + oA[p], ha[p]);
    cp_commit();
    {
        float4 wa, wb;
#pragma unroll
        for (int p = 0; p < 8; p++) {
            wa = *reinterpret_cast<const float4*>(bsrc[p]);
            wb = *reinterpret_cast<const float4*>(bsrc[p] + 4);
            *reinterpret_cast<uint4*>(smem + G2_B + oB[p]) = h16(wa, wb);
        }
    }
    cp_wait0();
    __syncthreads();

    const int KT = Ndim / 64;   // 22 stages
    float4 wga[4], wgb[4];
    for (int kt = 0; kt < KT; ++kt) {
        const int cur = (kt & 1) * G2_STAGE;
        const int nxt = ((kt + 1) & 1) * G2_STAGE;
        const bool more = (kt + 1 < KT);
        const int ko = (kt + 1) * 64;
        if (more) {
#pragma unroll
            for (int p = 0; p < 4; p++)
                cp16(sb + nxt + G2_A + oA[p], ha[p] + ko);
            cp_commit();
        }
#pragma unroll
        for (int c = 0; c < 4; c++) {
            uint32_t a[4][4], b[4][4];
            const uint32_t swA = (uint32_t)(((2 * c + hiA) ^ lx) << 4) + cur;
            const uint32_t swB = (uint32_t)(((2 * c + hiB) ^ lx) << 4) + cur;
#pragma unroll
            for (int mf = 0; mf < 4; mf++) ldsm4(a[mf], rA[mf] + swA);
#pragma unroll
            for (int h = 0; h < 4; h++) ldsm4(b[h], rB[h] + swB);
            if (c == 3) { cp_wait0(); __syncthreads(); }
#pragma unroll
            for (int mf = 0; mf < 4; mf++)
#pragma unroll
                for (int h = 0; h < 4; h++) {
                    mma16(acc[mf][2 * h],     a[mf], b[h][0], b[h][1]);
                    mma16(acc[mf][2 * h + 1], a[mf], b[h][2], b[h][3]);
                }
            if (more) {
                if (c == 0) {
#pragma unroll
                    for (int p = 0; p < 4; p++) {
                        wga[p] = *reinterpret_cast<const float4*>(bsrc[p] + ko);
                        wgb[p] = *reinterpret_cast<const float4*>(bsrc[p] + ko + 4);
                    }
                } else if (c == 1) {
#pragma unroll
                    for (int p = 0; p < 4; p++)
                        *reinterpret_cast<uint4*>(smem + nxt + G2_B + oB[p]) = h16(wga[p], wgb[p]);
#pragma unroll
                    for (int p = 0; p < 4; p++) {
                        wga[p] = *reinterpret_cast<const float4*>(bsrc[p + 4] + ko);
                        wgb[p] = *reinterpret_cast<const float4*>(bsrc[p + 4] + ko + 4);
                    }
                } else if (c == 2) {
#pragma unroll
                    for (int p = 0; p < 4; p++)
                        *reinterpret_cast<uint4*>(smem + nxt + G2_B + oB[p + 4]) = h16(wga[p], wgb[p]);
                }
            }
        }
    }

    // ---- gated atomic scatter-combine ----
#pragma unroll
    for (int mf = 0; mf < 4; mf++) {
#pragma unroll
        for (int half = 0; half < 2; half++) {
            const int grow = row0 + wm + mf * 16 + half * 8 + lr;
            if (grow >= cnt) continue;
            const int   tok  = g_rowtok[e * CAP + grow];
            const float gate = g_rowgate[e * CAP + grow];
            float* orow = out + (size_t)tok * Kdim + k0;
#pragma unroll
            for (int nf = 0; nf < 8; nf++) {
                const int col = wn + nf * 8 + 2 * lc;
                atomicAdd(orow + col,     gate * acc[mf][nf][half * 2]);
                atomicAdd(orow + col + 1, gate * acc[mf][nf][half * 2 + 1]);
            }
        }
    }
}

// ---------------------------------------------------------------------------
// Launch
// ---------------------------------------------------------------------------
extern "C" void kernel_launch(void* const* d_in, const int* in_sizes, int n_in,
                              void* d_out, int out_size) {
    const float* X    = (const float*)d_in[0];
    const int*   fidx = (const int*)  d_in[1];
    const float* fg   = (const float*)d_in[2];
    const float* GW   = (const float*)d_in[3];
    const float* UW   = (const float*)d_in[4];
    const float* DW   = (const float*)d_in[5];
    float* out = (float*)d_out;

    cudaFuncSetAttribute(k_gemm1, cudaFuncAttributeMaxDynamicSharedMemorySize, G1_SMEM);
    cudaFuncSetAttribute(k_gemm2, cudaFuncAttributeMaxDynamicSharedMemorySize, G2_SMEM);

    k_prep<<<(Mtok * Kdim / 4 + 255) / 256, 256>>>(out, X);
    k_route<<<(RROWS + 255) / 256, 256>>>(fidx, fg);

    dim3 g1(Ndim / 128, CAP / 128, NE);   // 11 x 8 x 8
    k_gemm1<<<g1, 256, G1_SMEM>>>(GW, UW);

    dim3 g2(Kdim / 256, CAP / 128, NE);   // 8 x 8 x 8
    k_gemm2<<<g2, 256, G2_SMEM>>>(DW, out);
}